// round 2
// baseline (speedup 1.0000x reference)
#include <cuda_runtime.h>

#define ALPHA_LRELU 0.8f
#define NODES_PER_BLOCK 8
#define NTHREADS 256

// Scratch for precomputed score-projection vectors (no allocs allowed).
__device__ __align__(16) float g_c1[128];   // W  @ a_x  (128)
__device__ __align__(16) float g_c2[128];   // W2 @ a_n  (128)

__global__ void precompute_kernel(const float* __restrict__ W,
                                  const float* __restrict__ W2,
                                  const float* __restrict__ a) {
    int k = threadIdx.x;  // 0..127
    float s1 = 0.f, s2 = 0.f;
#pragma unroll
    for (int d = 0; d < 64; ++d) {
        s1 += W [k * 64 + d] * a[d];
        s2 += W2[k * 64 + d] * a[64 + d];
    }
    g_c1[k] = s1;
    g_c2[k] = s2;
}

__device__ __forceinline__ float warp_sum(float v) {
    v += __shfl_xor_sync(0xffffffffu, v, 16);
    v += __shfl_xor_sync(0xffffffffu, v, 8);
    v += __shfl_xor_sync(0xffffffffu, v, 4);
    v += __shfl_xor_sync(0xffffffffu, v, 2);
    v += __shfl_xor_sync(0xffffffffu, v, 1);
    return v;
}

// Fused: scores -> leaky-relu -> ONLINE softmax -> aggregate(raw feat, edge)
//        -> block-wide GEMVs against W / W2 cached in shared memory.
// Phase A (warp == node): attention + raw-feature aggregation into smem.
//   Online-softmax keeps register usage ~35 (no 16-entry arrays, no spills).
// Phase B (block-wide):   [8 x 128] @ [128 x 128 (W|W2)] -> x and h_prime.
//   Each thread owns one output column for 4 nodes so W/W2 smem reads are
//   amortized 4x.
__global__ __launch_bounds__(NTHREADS, 2)
void gat_fused_kernel(const float* __restrict__ input,
                      const float* __restrict__ neigh,
                      const float* __restrict__ edge,
                      const float* __restrict__ W,
                      const float* __restrict__ W2,
                      const float* __restrict__ a,
                      float* __restrict__ out,
                      int N) {
    extern __shared__ float sh[];
    float* Wsh    = sh;                                   // 128*64 floats
    float* W2sh   = sh + 8192;                            // 128*64 floats
    float* in_sh  = sh + 16384;                           // 8*128
    float* agg_sh = sh + 16384 + NODES_PER_BLOCK * 128;   // 8*128

    const int tid = threadIdx.x;
    // Cooperative weight load (once per persistent block).
    {
        const float4* Wg  = (const float4*)W;
        const float4* W2g = (const float4*)W2;
        float4* Ws4  = (float4*)Wsh;
        float4* W2s4 = (float4*)W2sh;
        for (int i = tid; i < 2048; i += NTHREADS) Ws4[i]  = Wg[i];
        for (int i = tid; i < 2048; i += NTHREADS) W2s4[i] = W2g[i];
    }
    __syncthreads();

    const int w = tid >> 5;        // warp id = local node id
    const int l = tid & 31;        // lane

    const float4 c1v = ((const float4*)g_c1)[l];
    const float4 c2v = ((const float4*)g_c2)[l];
    const float  aev = a[128 + l];          // a_e[l]

    // Phase-B mapping: each thread owns one output column for 4 nodes.
    const int col  = tid & 127;             // 0..127
    const int r0   = (tid >> 7) * 4;        // nodes r0..r0+3 of this block's 8
    const int c    = col & 63;
    const float* Msh  = (col < 64) ? Wsh   : W2sh;
    const float* srcS = (col < 64) ? in_sh : agg_sh;

    for (int n0 = blockIdx.x * NODES_PER_BLOCK; n0 < N;
         n0 += gridDim.x * NODES_PER_BLOCK) {
        const int n = n0 + w;

        if (n < N) {
            // ---- Phase A: attention for node n (one warp, online softmax) ----
            const float4 in4 = ((const float4*)(input + (long long)n * 128))[l];
            ((float4*)(in_sh + w * 128))[l] = in4;
            const float sx = warp_sum(in4.x * c1v.x + in4.y * c1v.y +
                                      in4.z * c1v.z + in4.w * c1v.w);

            const float4* nrow = (const float4*)(neigh + (long long)n * 2048);
            const float*  erow = edge + (long long)n * 512;

            float m = -1e30f, sum = 0.f, agge = 0.f;
            float4 agg = make_float4(0.f, 0.f, 0.f, 0.f);
#pragma unroll
            for (int s = 0; s < 16; ++s) {
                const float4 v = nrow[s * 32 + l];
                const float  e = erow[s * 32 + l];
                const float q = warp_sum(v.x * c2v.x + v.y * c2v.y +
                                         v.z * c2v.z + v.w * c2v.w + e * aev);
                float t = sx + q;
                t = (t > 0.f) ? t : ALPHA_LRELU * t;      // leaky relu score
                // online softmax update (sc identical across lanes)
                const float m_new = fmaxf(m, t);
                const float scale = __expf(m - m_new);    // 1 if m unchanged
                const float p     = __expf(t - m_new);
                sum  = sum * scale + p;
                agg.x = agg.x * scale + p * v.x;
                agg.y = agg.y * scale + p * v.y;
                agg.z = agg.z * scale + p * v.z;
                agg.w = agg.w * scale + p * v.w;
                agge  = agge * scale + p * e;
                m = m_new;
            }
            const float inv = 1.f / sum;
            agg.x *= inv; agg.y *= inv; agg.z *= inv; agg.w *= inv;
            ((float4*)(agg_sh + w * 128))[l] = agg;
            out[(long long)n * 160 + 128 + l] = agge * inv;   // h_edge
        }
        __syncthreads();

        // ---- Phase B: block-wide GEMV for 8 nodes ----
        float acc0 = 0.f, acc1 = 0.f, acc2 = 0.f, acc3 = 0.f;
        const float* s0 = srcS + (r0 + 0) * 128;
        const float* s1 = srcS + (r0 + 1) * 128;
        const float* s2 = srcS + (r0 + 2) * 128;
        const float* s3 = srcS + (r0 + 3) * 128;
#pragma unroll 8
        for (int k = 0; k < 128; ++k) {
            const float wk = Msh[k * 64 + c];
            acc0 += wk * s0[k];
            acc1 += wk * s1[k];
            acc2 += wk * s2[k];
            acc3 += wk * s3[k];
        }
        {
            int nn;
            nn = n0 + r0 + 0; if (nn < N) out[(long long)nn * 160 + col] = acc0;
            nn = n0 + r0 + 1; if (nn < N) out[(long long)nn * 160 + col] = acc1;
            nn = n0 + r0 + 2; if (nn < N) out[(long long)nn * 160 + col] = acc2;
            nn = n0 + r0 + 3; if (nn < N) out[(long long)nn * 160 + col] = acc3;
        }
        __syncthreads();  // protect in_sh/agg_sh before next iteration
    }
}

extern "C" void kernel_launch(void* const* d_in, const int* in_sizes, int n_in,
                              void* d_out, int out_size) {
    const float* input = (const float*)d_in[0];
    const float* neigh = (const float*)d_in[1];
    const float* edge  = (const float*)d_in[2];
    const float* W     = (const float*)d_in[3];
    const float* W2    = (const float*)d_in[4];
    const float* a     = (const float*)d_in[5];
    float* out = (float*)d_out;

    const int N = in_sizes[0] / 128;

    const int smem_bytes = (8192 + 8192 + NODES_PER_BLOCK * 128 * 2) * 4;  // 73728
    cudaFuncSetAttribute(gat_fused_kernel,
                         cudaFuncAttributeMaxDynamicSharedMemorySize, smem_bytes);

    precompute_kernel<<<1, 128>>>(W, W2, a);
    gat_fused_kernel<<<296, NTHREADS, smem_bytes>>>(input, neigh, edge, W, W2, a,
                                                    out, N);
}

// round 4
// speedup vs baseline: 1.0100x; 1.0100x over previous
#include <cuda_runtime.h>

#define ALPHA_LRELU 0.8f
#define NODES_PER_BLOCK 8
#define NTHREADS 256
#define WT_STRIDE 132   // 128 + 4 pad: conflict-free LDS.128 column reads

// Scratch for precomputed score-projection vectors (no allocs allowed).
__device__ __align__(16) float g_c1[128];   // W  @ a_x  (128)
__device__ __align__(16) float g_c2[128];   // W2 @ a_n  (128)

__global__ void precompute_kernel(const float* __restrict__ W,
                                  const float* __restrict__ W2,
                                  const float* __restrict__ a) {
    int k = threadIdx.x;  // 0..127
    float s1 = 0.f, s2 = 0.f;
#pragma unroll
    for (int d = 0; d < 64; ++d) {
        s1 += W [k * 64 + d] * a[d];
        s2 += W2[k * 64 + d] * a[64 + d];
    }
    g_c1[k] = s1;
    g_c2[k] = s2;
}

__device__ __forceinline__ float warp_sum(float v) {
    v += __shfl_xor_sync(0xffffffffu, v, 16);
    v += __shfl_xor_sync(0xffffffffu, v, 8);
    v += __shfl_xor_sync(0xffffffffu, v, 4);
    v += __shfl_xor_sync(0xffffffffu, v, 2);
    v += __shfl_xor_sync(0xffffffffu, v, 1);
    return v;
}

// Phase A (warp == node): attention (online softmax) + raw-feature aggregation.
// Phase B (block-wide): [8 x 128] @ (W | W2) with W^T/W2^T in padded smem so
//   every access is a float4 (weights: conflict-free LDS.128 column reads;
//   node vectors: 128B broadcasts). 4x fewer LDS instructions than scalar.
__global__ __launch_bounds__(NTHREADS, 2)
void gat_fused_kernel(const float* __restrict__ input,
                      const float* __restrict__ neigh,
                      const float* __restrict__ edge,
                      const float* __restrict__ W,
                      const float* __restrict__ W2,
                      const float* __restrict__ a,
                      float* __restrict__ out,
                      int N) {
    extern __shared__ float sh[];
    float* Wt   = sh;                       // 64 x WT_STRIDE (W^T, padded)
    float* W2t  = sh + 64 * WT_STRIDE;      // 64 x WT_STRIDE
    float* in_sh  = sh + 2 * 64 * WT_STRIDE;               // 8*128
    float* agg_sh = sh + 2 * 64 * WT_STRIDE + NODES_PER_BLOCK * 128;

    const int tid = threadIdx.x;
    // Cooperative transposed weight load (once per persistent block).
    // W is [128][64] row-major; write Wt[d][k] with padded stride.
    for (int i = tid; i < 2048; i += NTHREADS) {          // 2048 float4 rows
        const int k  = i >> 4;          // 0..127
        const int d0 = (i & 15) * 4;    // 0,4,...,60
        const float4 w4  = ((const float4*)W)[i];
        const float4 w24 = ((const float4*)W2)[i];
        Wt [(d0 + 0) * WT_STRIDE + k] = w4.x;
        Wt [(d0 + 1) * WT_STRIDE + k] = w4.y;
        Wt [(d0 + 2) * WT_STRIDE + k] = w4.z;
        Wt [(d0 + 3) * WT_STRIDE + k] = w4.w;
        W2t[(d0 + 0) * WT_STRIDE + k] = w24.x;
        W2t[(d0 + 1) * WT_STRIDE + k] = w24.y;
        W2t[(d0 + 2) * WT_STRIDE + k] = w24.z;
        W2t[(d0 + 3) * WT_STRIDE + k] = w24.w;
    }
    __syncthreads();

    const int w = tid >> 5;        // warp id = local node id
    const int l = tid & 31;        // lane

    const float4 c1v = ((const float4*)g_c1)[l];
    const float4 c2v = ((const float4*)g_c2)[l];
    const float  aev = a[128 + l];          // a_e[l]

    // Phase-B mapping: each thread owns one output column for 4 nodes.
    const int col  = tid & 127;             // 0..127
    const int r0   = (tid >> 7) * 4;        // nodes r0..r0+3 of this block's 8
    const int c    = col & 63;
    const float* Mrow = ((col < 64) ? Wt   : W2t) + c * WT_STRIDE;
    const float* srcS = (col < 64) ? in_sh : agg_sh;

    for (int n0 = blockIdx.x * NODES_PER_BLOCK; n0 < N;
         n0 += gridDim.x * NODES_PER_BLOCK) {
        const int n = n0 + w;

        if (n < N) {
            // ---- Phase A: attention for node n (one warp, online softmax) ----
            const float4 in4 = ((const float4*)(input + (long long)n * 128))[l];
            ((float4*)(in_sh + w * 128))[l] = in4;
            const float sx = warp_sum(in4.x * c1v.x + in4.y * c1v.y +
                                      in4.z * c1v.z + in4.w * c1v.w);

            const float4* nrow = (const float4*)(neigh + (long long)n * 2048);
            const float*  erow = edge + (long long)n * 512;

            float m = -1e30f, sum = 0.f, agge = 0.f;
            float4 agg = make_float4(0.f, 0.f, 0.f, 0.f);
#pragma unroll
            for (int s = 0; s < 16; ++s) {
                const float4 v = nrow[s * 32 + l];
                const float  e = erow[s * 32 + l];
                const float q = warp_sum(v.x * c2v.x + v.y * c2v.y +
                                         v.z * c2v.z + v.w * c2v.w + e * aev);
                float t = sx + q;
                t = (t > 0.f) ? t : ALPHA_LRELU * t;      // leaky relu score
                // online softmax update (identical across lanes)
                const float m_new = fmaxf(m, t);
                const float scale = __expf(m - m_new);
                const float p     = __expf(t - m_new);
                sum  = sum * scale + p;
                agg.x = agg.x * scale + p * v.x;
                agg.y = agg.y * scale + p * v.y;
                agg.z = agg.z * scale + p * v.z;
                agg.w = agg.w * scale + p * v.w;
                agge  = agge * scale + p * e;
                m = m_new;
            }
            const float inv = 1.f / sum;
            agg.x *= inv; agg.y *= inv; agg.z *= inv; agg.w *= inv;
            ((float4*)(agg_sh + w * 128))[l] = agg;
            out[(long long)n * 160 + 128 + l] = agge * inv;   // h_edge
        }
        __syncthreads();

        // ---- Phase B: block-wide GEMV for 8 nodes, all-float4 smem ----
        float acc0 = 0.f, acc1 = 0.f, acc2 = 0.f, acc3 = 0.f;
        const float4* m4 = (const float4*)Mrow;            // 16B-aligned (132%4==0)
        const float4* s0 = (const float4*)(srcS + (r0 + 0) * 128);
        const float4* s1 = (const float4*)(srcS + (r0 + 1) * 128);
        const float4* s2 = (const float4*)(srcS + (r0 + 2) * 128);
        const float4* s3 = (const float4*)(srcS + (r0 + 3) * 128);
#pragma unroll 8
        for (int k = 0; k < 32; ++k) {
            const float4 wk = m4[k];
            const float4 a0 = s0[k], a1 = s1[k], a2 = s2[k], a3 = s3[k];
            acc0 += wk.x * a0.x + wk.y * a0.y + wk.z * a0.z + wk.w * a0.w;
            acc1 += wk.x * a1.x + wk.y * a1.y + wk.z * a1.z + wk.w * a1.w;
            acc2 += wk.x * a2.x + wk.y * a2.y + wk.z * a2.z + wk.w * a2.w;
            acc3 += wk.x * a3.x + wk.y * a3.y + wk.z * a3.z + wk.w * a3.w;
        }
        {
            int nn;
            nn = n0 + r0 + 0; if (nn < N) out[(long long)nn * 160 + col] = acc0;
            nn = n0 + r0 + 1; if (nn < N) out[(long long)nn * 160 + col] = acc1;
            nn = n0 + r0 + 2; if (nn < N) out[(long long)nn * 160 + col] = acc2;
            nn = n0 + r0 + 3; if (nn < N) out[(long long)nn * 160 + col] = acc3;
        }
        __syncthreads();  // protect in_sh/agg_sh before next iteration
    }
}

extern "C" void kernel_launch(void* const* d_in, const int* in_sizes, int n_in,
                              void* d_out, int out_size) {
    const float* input = (const float*)d_in[0];
    const float* neigh = (const float*)d_in[1];
    const float* edge  = (const float*)d_in[2];
    const float* W     = (const float*)d_in[3];
    const float* W2    = (const float*)d_in[4];
    const float* a     = (const float*)d_in[5];
    float* out = (float*)d_out;

    const int N = in_sizes[0] / 128;

    const int smem_bytes = (2 * 64 * WT_STRIDE + NODES_PER_BLOCK * 128 * 2) * 4;
    cudaFuncSetAttribute(gat_fused_kernel,
                         cudaFuncAttributeMaxDynamicSharedMemorySize, smem_bytes);

    precompute_kernel<<<1, 128>>>(W, W2, a);
    gat_fused_kernel<<<296, NTHREADS, smem_bytes>>>(input, neigh, edge, W, W2, a,
                                                    out, N);
}